// round 1
// baseline (speedup 1.0000x reference)
#include <cuda_runtime.h>

// Problem dims
#define BB 16
#define TT 1024
#define HH 512
#define AA 80
#define UU 600
#define KG 10
#define PP 30

// Scratch: exp(params) padded to 32 per row. Device globals are allowed.
__device__ float g_abk[(size_t)BB * TT * 32];

// ---------------------------------------------------------------------------
// Kernel 1: params[b,t,p] = exp( lstm[b,t,:] . W[:,p] + bias[p] )
// Grid: (TT/128, BB), 256 threads. Thread tile: 4t x 4p.
// ---------------------------------------------------------------------------
__global__ __launch_bounds__(256) void k1_params(
    const float* __restrict__ lstm,
    const float* __restrict__ W,
    const float* __restrict__ bias)
{
    __shared__ float sXT[64][132];   // [h][t], padded for conflicts + 16B align
    __shared__ float sW[64][32];     // [h][p]

    const int tid = threadIdx.x;
    const int tg  = tid & 31;        // t-group: owns 4 consecutive t
    const int pg  = tid >> 5;        // p-group 0..7: owns 4 consecutive p
    const int b   = blockIdx.y;
    const int t0  = blockIdx.x * 128;
    const float* lbase = lstm + ((size_t)b * TT + t0) * HH;

    float acc[4][4];
#pragma unroll
    for (int i = 0; i < 4; ++i)
#pragma unroll
        for (int j = 0; j < 4; ++j) acc[i][j] = 0.f;

    for (int hc = 0; hc < HH / 64; ++hc) {
        __syncthreads();
        // Stage X^T: 128 t x 64 h. Consecutive tid -> consecutive h (coalesced).
        for (int idx = tid; idx < 128 * 64; idx += 256) {
            int t = idx >> 6, h = idx & 63;
            sXT[h][t] = lbase[(size_t)t * HH + hc * 64 + h];
        }
        // Stage W chunk: 64 h x 30 p (pad to 32, zero-fill).
        for (int idx = tid; idx < 64 * 32; idx += 256) {
            int h = idx >> 5, p = idx & 31;
            sW[h][p] = (p < PP) ? W[(hc * 64 + h) * PP + p] : 0.f;
        }
        __syncthreads();
#pragma unroll 8
        for (int h = 0; h < 64; ++h) {
            float4 x = *(const float4*)&sXT[h][tg * 4];
            float4 w = *(const float4*)&sW[h][pg * 4];   // warp-broadcast
            acc[0][0] += x.x * w.x; acc[0][1] += x.x * w.y;
            acc[0][2] += x.x * w.z; acc[0][3] += x.x * w.w;
            acc[1][0] += x.y * w.x; acc[1][1] += x.y * w.y;
            acc[1][2] += x.y * w.z; acc[1][3] += x.y * w.w;
            acc[2][0] += x.z * w.x; acc[2][1] += x.z * w.y;
            acc[2][2] += x.z * w.z; acc[2][3] += x.z * w.w;
            acc[3][0] += x.w * w.x; acc[3][1] += x.w * w.y;
            acc[3][2] += x.w * w.z; acc[3][3] += x.w * w.w;
        }
    }

#pragma unroll
    for (int i = 0; i < 4; ++i) {
        int t = t0 + tg * 4 + i;
#pragma unroll
        for (int j = 0; j < 4; ++j) {
            int p = pg * 4 + j;
            if (p < PP)
                g_abk[((size_t)b * TT + t) * 32 + p] = __expf(acc[i][j] + bias[p]);
        }
    }
}

// ---------------------------------------------------------------------------
// Kernel 2: windowed phi + out = phi @ char_seq
//   phi[t,u] = sum_m a_m * exp(-b_m * (k_m - u)^2); exactly negligible for
//   u > k + sqrt(40/b) (mass < 1e-15), so we cut the u-loop per tile.
// Grid: (TT/64, BB), 256 threads. Out tile: 64t x 80a, thread 4t x 5a.
// ---------------------------------------------------------------------------
__global__ __launch_bounds__(256) void k2_window(
    const float* __restrict__ chs,
    float* __restrict__ out)
{
    __shared__ float sABK[64][32];
    __shared__ float sChar[16][80];
    __shared__ float sPhi[16][68];   // [u][t], padded (272B rows, 16B aligned)
    __shared__ int   sUblk;

    const int tid = threadIdx.x;
    const int b   = blockIdx.y;
    const int t0  = blockIdx.x * 64;

    for (int idx = tid; idx < 64 * 32; idx += 256) {
        int t = idx >> 5, p = idx & 31;
        sABK[t][p] = g_abk[((size_t)b * TT + t0 + t) * 32 + p];
    }
    if (tid == 0) sUblk = 1;
    __syncthreads();

    if (tid < 64) {
        float um = 1.f;
#pragma unroll
        for (int m = 0; m < KG; ++m) {
            float bm = sABK[tid][10 + m];
            float km = sABK[tid][20 + m];
            um = fmaxf(um, km + sqrtf(40.f / bm));
        }
        int c = (int)fminf(ceilf(um) + 2.f, (float)UU);
        atomicMax(&sUblk, c);
    }
    __syncthreads();
    const int Ublk = sUblk;

    // phi role: thread owns (t_phi, 4 u's per chunk); a,b,k live in registers
    const int t_phi = tid & 63;
    const int uq    = tid >> 6;      // 0..3
    float ra[KG], rb[KG], rk[KG];
#pragma unroll
    for (int m = 0; m < KG; ++m) {
        ra[m] = sABK[t_phi][m];
        rb[m] = sABK[t_phi][10 + m];
        rk[m] = sABK[t_phi][20 + m];
    }

    // gemm role
    const int tg2 = tid & 15;        // 4 consecutive t
    const int ag  = tid >> 4;        // 0..15 -> 5 consecutive a
    float accO[4][5];
#pragma unroll
    for (int i = 0; i < 4; ++i)
#pragma unroll
        for (int j = 0; j < 5; ++j) accO[i][j] = 0.f;

    for (int u0 = 0; u0 < Ublk; u0 += 16) {
        __syncthreads();             // prior GEMM reads done before overwrite
        // stage char tile (zero-pad past U)
        for (int idx = tid; idx < 16 * 80; idx += 256) {
            int u = idx / 80, a = idx - u * 80;
            int gu = u0 + u;
            sChar[u][a] = (gu < UU) ? chs[((size_t)b * UU + gu) * AA + a] : 0.f;
        }
        // compute phi for 4 u's of this thread's row
#pragma unroll
        for (int r = 0; r < 4; ++r) {
            float uf = (float)(u0 + uq * 4 + r);
            float s = 0.f;
#pragma unroll
            for (int m = 0; m < KG; ++m) {
                float d = rk[m] - uf;
                s += ra[m] * __expf(-rb[m] * d * d);
            }
            sPhi[uq * 4 + r][t_phi] = s;
        }
        __syncthreads();
        // micro-GEMM: 16 u steps
#pragma unroll 4
        for (int u = 0; u < 16; ++u) {
            float4 ph = *(const float4*)&sPhi[u][tg2 * 4];
            float c0 = sChar[u][ag * 5 + 0];
            float c1 = sChar[u][ag * 5 + 1];
            float c2 = sChar[u][ag * 5 + 2];
            float c3 = sChar[u][ag * 5 + 3];
            float c4 = sChar[u][ag * 5 + 4];
            accO[0][0] += ph.x * c0; accO[0][1] += ph.x * c1; accO[0][2] += ph.x * c2;
            accO[0][3] += ph.x * c3; accO[0][4] += ph.x * c4;
            accO[1][0] += ph.y * c0; accO[1][1] += ph.y * c1; accO[1][2] += ph.y * c2;
            accO[1][3] += ph.y * c3; accO[1][4] += ph.y * c4;
            accO[2][0] += ph.z * c0; accO[2][1] += ph.z * c1; accO[2][2] += ph.z * c2;
            accO[2][3] += ph.z * c3; accO[2][4] += ph.z * c4;
            accO[3][0] += ph.w * c0; accO[3][1] += ph.w * c1; accO[3][2] += ph.w * c2;
            accO[3][3] += ph.w * c3; accO[3][4] += ph.w * c4;
        }
    }

#pragma unroll
    for (int i = 0; i < 4; ++i) {
        int t = t0 + tg2 * 4 + i;
#pragma unroll
        for (int j = 0; j < 5; ++j) {
            out[((size_t)b * TT + t) * AA + ag * 5 + j] = accO[i][j];
        }
    }
}

extern "C" void kernel_launch(void* const* d_in, const int* in_sizes, int n_in,
                              void* d_out, int out_size)
{
    const float* lstm = (const float*)d_in[0];  // [16,1024,512]
    const float* chs  = (const float*)d_in[1];  // [16,600,80]
    const float* W    = (const float*)d_in[2];  // [512,30]
    const float* bias = (const float*)d_in[3];  // [30]
    float* out = (float*)d_out;                 // [16,1024,80]
    (void)in_sizes; (void)n_in; (void)out_size;

    k1_params<<<dim3(TT / 128, BB), 256>>>(lstm, W, bias);
    k2_window<<<dim3(TT / 64, BB), 256>>>(chs, out);
}

// round 2
// speedup vs baseline: 1.0479x; 1.0479x over previous
#include <cuda_runtime.h>

#define BB 16
#define TT 1024
#define HH 512
#define AA 80
#define UU 600
#define KG 10
#define PP 30
#define NROWS (BB * TT)

// Scratch: exp(params) padded to 32 per row.
__device__ float g_abk[(size_t)NROWS * 32];

// Packed f32x2 FMA: d += a * b (two lanes)
#define FMA2(d, a, b) \
    asm("fma.rn.f32x2 %0, %1, %2, %0;" : "+l"(d) : "l"(a), "l"(b))

union F4U2 { float4 f4; unsigned long long u2[2]; };
union U64F2 { unsigned long long u; float2 f2; };

// ---------------------------------------------------------------------------
// Kernel 1: abk[r,p] = exp( lstm[r,:] . W[:,p] + bias[p] ), rows flattened.
// Grid: 256 blocks (64 rows each), 128 threads. Thread tile 4t x 4p via FFMA2
// (t-pairs packed). W duplicated in smem so the b-operand needs no MOV packs.
// ---------------------------------------------------------------------------
__global__ __launch_bounds__(128) void k1_params(
    const float* __restrict__ lstm,
    const float* __restrict__ W,
    const float* __restrict__ bias)
{
    __shared__ float sXT[64][68];   // [h][t], 272B rows: 16B-aligned, STS.128-conflict-free
    __shared__ float sW2[64][64];   // [h][ pg*8 + 2j + dup ] = W[h][4pg+j] duplicated

    const int tid = threadIdx.x;
    const int tg  = tid & 15;       // 4 consecutive t
    const int pg  = tid >> 4;       // 0..7 -> 4 consecutive p
    const int row0 = blockIdx.x * 64;
    const float* lbase = lstm + (size_t)row0 * HH;

    unsigned long long acc[2][4];   // [t-pair][j]
#pragma unroll
    for (int i = 0; i < 2; ++i)
#pragma unroll
        for (int j = 0; j < 4; ++j) acc[i][j] = 0ULL;

    const int hlane = tid & 31;     // h lane within chunk
    const int wq    = tid >> 5;     // warp id 0..3

    for (int hc = 0; hc < HH / 64; ++hc) {
        __syncthreads();
        // --- stage X transposed: 64 h x 64 t.
        // Each iter: 4 coalesced LDG.32 (lanes span h) + 1 conflict-free STS.128 (4 t).
#pragma unroll
        for (int it = 0; it < 8; ++it) {
            int q = wq + 4 * (it & 3);         // t-quad 0..15
            int h = hlane + 32 * (it >> 2);    // 0..63
            float4 xv;
            const float* src = lbase + (size_t)(4 * q) * HH + hc * 64 + h;
            xv.x = src[0 * HH];
            xv.y = src[1 * HH];
            xv.z = src[2 * HH];
            xv.w = src[3 * HH];
            *(float4*)&sXT[h][4 * q] = xv;
        }
        // --- stage W duplicated: 64 h x (8 pg x 8 dup-cols)
        for (int idx = tid; idx < 64 * 64; idx += 128) {
            int h = idx >> 6, c = idx & 63;
            int p = (c >> 3) * 4 + ((c & 7) >> 1);
            sW2[h][c] = (p < PP) ? W[(hc * 64 + h) * PP + p] : 0.f;
        }
        __syncthreads();

#pragma unroll 16
        for (int h = 0; h < 64; ++h) {
            F4U2 x;  x.f4  = *(const float4*)&sXT[h][tg * 4];
            F4U2 wa; wa.f4 = *(const float4*)&sW2[h][pg * 8];      // (w0,w0,w1,w1)
            F4U2 wb; wb.f4 = *(const float4*)&sW2[h][pg * 8 + 4];  // (w2,w2,w3,w3)
            FMA2(acc[0][0], x.u2[0], wa.u2[0]);
            FMA2(acc[0][1], x.u2[0], wa.u2[1]);
            FMA2(acc[0][2], x.u2[0], wb.u2[0]);
            FMA2(acc[0][3], x.u2[0], wb.u2[1]);
            FMA2(acc[1][0], x.u2[1], wa.u2[0]);
            FMA2(acc[1][1], x.u2[1], wa.u2[1]);
            FMA2(acc[1][2], x.u2[1], wb.u2[0]);
            FMA2(acc[1][3], x.u2[1], wb.u2[1]);
        }
    }

#pragma unroll
    for (int j = 0; j < 4; ++j) {
        int p = pg * 4 + j;
        if (p < PP) {
            float bs = bias[p];
#pragma unroll
            for (int tp = 0; tp < 2; ++tp) {
                U64F2 v; v.u = acc[tp][j];
                int r = row0 + tg * 4 + tp * 2;
                g_abk[(size_t)r * 32 + p]       = __expf(v.f2.x + bs);
                g_abk[(size_t)(r + 1) * 32 + p] = __expf(v.f2.y + bs);
            }
        }
    }
}

// ---------------------------------------------------------------------------
// Kernel 2: windowed phi + out = phi @ char_seq.
// Grid: 512 blocks (32 rows each), 256 threads. Double-buffered char/phi smem,
// one sync per u-chunk; char chunk 0 prefetched before the abk load.
// ---------------------------------------------------------------------------
__global__ __launch_bounds__(256) void k2_window(
    const float* __restrict__ chs,
    float* __restrict__ out)
{
    __shared__ float sABK[32 * 32];
    __shared__ float sChar[2][16][80];
    __shared__ float sPhi[2][16][34];
    __shared__ int   sUblk;

    const int tid  = threadIdx.x;
    const int row0 = blockIdx.x * 32;
    const int b    = row0 >> 10;
    const float* cb = chs + (size_t)b * UU * AA;

    // --- prefetch char chunk 0 (independent of abk)
#pragma unroll
    for (int i = 0; i < 5; ++i) {
        int idx = tid + 256 * i;
        int u = idx / 80, a = idx - u * 80;
        sChar[0][u][a] = cb[u * AA + a];          // u < 16 < UU always
    }
    // --- load abk tile (32 rows x 32)
    *(float4*)&sABK[tid * 4] = *(const float4*)&g_abk[(size_t)row0 * 32 + tid * 4];
    if (tid == 0) sUblk = 16;
    __syncthreads();

    // phi role: t = tid&31, each thread 2 u's per chunk
    const int t_phi = tid & 31;
    const int uq    = tid >> 5;                   // 0..7
    float ra[KG], rb[KG], rk[KG];
#pragma unroll
    for (int m = 0; m < KG; ++m) {
        ra[m] = sABK[t_phi * 32 + m];
        rb[m] = sABK[t_phi * 32 + 10 + m];
        rk[m] = sABK[t_phi * 32 + 20 + m];
    }
    // cutoff: threads 0..31 compute their row's reach
    if (tid < 32) {
        float um = 1.f;
#pragma unroll
        for (int m = 0; m < KG; ++m)
            um = fmaxf(um, rk[m] + sqrtf(40.f / rb[m]));
        atomicMax(&sUblk, (int)fminf(ceilf(um) + 2.f, (float)UU));
    }
    // phi chunk 0
#pragma unroll
    for (int r = 0; r < 2; ++r) {
        float uf = (float)(uq * 2 + r);
        float s = 0.f;
#pragma unroll
        for (int m = 0; m < KG; ++m) {
            float d = rk[m] - uf;
            s += ra[m] * __expf(-rb[m] * d * d);
        }
        sPhi[0][uq * 2 + r][t_phi] = s;
    }
    __syncthreads();

    const int nch = (sUblk + 15) >> 4;

    // gemm role: 2t x 5a per thread
    const int tg2 = tid & 15;
    const int ag  = tid >> 4;
    float accO[2][5];
#pragma unroll
    for (int i = 0; i < 2; ++i)
#pragma unroll
        for (int j = 0; j < 5; ++j) accO[i][j] = 0.f;

    for (int c = 0; c < nch; ++c) {
        int cur = c & 1;
        if (c + 1 < nch) {
            int nxt = cur ^ 1;
            int u0  = (c + 1) * 16;
            // stage next char chunk
#pragma unroll
            for (int i = 0; i < 5; ++i) {
                int idx = tid + 256 * i;
                int u = idx / 80, a = idx - u * 80;
                int gu = u0 + u;
                sChar[nxt][u][a] = (gu < UU) ? cb[gu * AA + a] : 0.f;
            }
            // next phi
#pragma unroll
            for (int r = 0; r < 2; ++r) {
                float uf = (float)(u0 + uq * 2 + r);
                float s = 0.f;
#pragma unroll
                for (int m = 0; m < KG; ++m) {
                    float d = rk[m] - uf;
                    s += ra[m] * __expf(-rb[m] * d * d);
                }
                sPhi[nxt][uq * 2 + r][t_phi] = s;
            }
        }
        // micro-GEMM over 16 u
#pragma unroll 4
        for (int u = 0; u < 16; ++u) {
            float2 ph = *(const float2*)&sPhi[cur][u][tg2 * 2];
            float c0 = sChar[cur][u][ag * 5 + 0];
            float c1 = sChar[cur][u][ag * 5 + 1];
            float c2 = sChar[cur][u][ag * 5 + 2];
            float c3 = sChar[cur][u][ag * 5 + 3];
            float c4 = sChar[cur][u][ag * 5 + 4];
            accO[0][0] += ph.x * c0; accO[0][1] += ph.x * c1;
            accO[0][2] += ph.x * c2; accO[0][3] += ph.x * c3;
            accO[0][4] += ph.x * c4;
            accO[1][0] += ph.y * c0; accO[1][1] += ph.y * c1;
            accO[1][2] += ph.y * c2; accO[1][3] += ph.y * c3;
            accO[1][4] += ph.y * c4;
        }
        __syncthreads();
    }

#pragma unroll
    for (int i = 0; i < 2; ++i) {
        int r = row0 + tg2 * 2 + i;
#pragma unroll
        for (int j = 0; j < 5; ++j)
            out[(size_t)r * AA + ag * 5 + j] = accO[i][j];
    }
}

extern "C" void kernel_launch(void* const* d_in, const int* in_sizes, int n_in,
                              void* d_out, int out_size)
{
    const float* lstm = (const float*)d_in[0];  // [16,1024,512]
    const float* chs  = (const float*)d_in[1];  // [16,600,80]
    const float* W    = (const float*)d_in[2];  // [512,30]
    const float* bias = (const float*)d_in[3];  // [30]
    float* out = (float*)d_out;                 // [16,1024,80]
    (void)in_sizes; (void)n_in; (void)out_size;

    k1_params<<<256, 128>>>(lstm, W, bias);
    k2_window<<<512, 256>>>(chs, out);
}

// round 3
// speedup vs baseline: 1.5764x; 1.5043x over previous
#include <cuda_runtime.h>
#include <cstdint>

#define BB 16
#define TT 1024
#define HH 512
#define AA 80
#define UU 600
#define PP 30

// W duplicated for FFMA2 b-operands: g_W2[h][pg*8 + 2j + d] = W[h][pg*4+j]
__device__ __align__(16) float g_W2[HH * 64];

__global__ void k0_dupW(const float* __restrict__ W) {
    int idx = blockIdx.x * 256 + threadIdx.x;     // 512*64 = 32768
    int h = idx >> 6, c = idx & 63;
    int p = (c >> 3) * 4 + ((c & 7) >> 1);
    g_W2[idx] = (p < PP) ? W[h * PP + p] : 0.f;
}

#define FMA2(d, a, b) asm("fma.rn.f32x2 %0, %1, %2, %0;" : "+l"(d) : "l"(a), "l"(b))
#define EX2A(d, a)    asm("ex2.approx.f32 %0, %1;" : "=f"(d) : "f"(a))

__device__ __forceinline__ void cpa16(uint32_t dst, const void* src) {
    asm volatile("cp.async.cg.shared.global [%0], [%1], 16;" :: "r"(dst), "l"(src));
}
#define CPA_COMMIT() asm volatile("cp.async.commit_group;")
#define CPA_WAIT0()  asm volatile("cp.async.wait_group 0;")

union F4U2  { float4 f4; unsigned long long u2[2]; };
union U64F2 { unsigned long long u; float2 f2; };

// smem layout (float offsets), all 16B-aligned
#define XT_OFF   0          // 2 * 64*68  = 8704
#define W2_OFF   8704       // 2 * 64*64  = 8192
#define CH_OFF   16896      // 2 * 16*80  = 2560
#define PH_OFF   19456      // 2 * 16*68  = 2176
#define ABK_OFF  21632      // 64*33      = 2112
#define UB_OFF   23744
#define SMEM_FLOATS 23748
#define SMEM_BYTES (SMEM_FLOATS * 4)

__global__ __launch_bounds__(128) void fused(
    const float* __restrict__ lstm,
    const float* __restrict__ chs,
    const float* __restrict__ bias,
    float* __restrict__ out)
{
    extern __shared__ float S[];
    int* iUblk = (int*)&S[UB_OFF];
    const int tid  = threadIdx.x;
    const int row0 = blockIdx.x * 64;
    const int b    = blockIdx.x >> 4;
    const float* lbase = lstm + (size_t)row0 * HH;
    const float* cb    = chs + (size_t)b * UU * AA;
    const uint32_t sbase = (uint32_t)__cvta_generic_to_shared(S);

    if (tid == 0) *iUblk = 16;

    const int tg = tid & 15, pg = tid >> 4;       // GEMM1: 4t x 4p tile
    const int hlane = tid & 31, wq = tid >> 5;

    float bj[4];
#pragma unroll
    for (int j = 0; j < 4; ++j) {
        int p = pg * 4 + j;
        bj[j] = (p < PP) ? bias[p] : 0.f;
    }

    unsigned long long acc[2][4];
#pragma unroll
    for (int i = 0; i < 2; ++i)
#pragma unroll
        for (int j = 0; j < 4; ++j) acc[i][j] = 0ULL;

    float xr[8][4];   // reg staging buffer: one 64h x 64t chunk slice per thread

#define LDG_X(hc) do {                                                        \
    _Pragma("unroll")                                                         \
    for (int it = 0; it < 8; ++it) {                                          \
        int q = wq + 4 * (it & 3);                                            \
        int h = hlane + 32 * (it >> 2);                                       \
        const float* src = lbase + (size_t)(4 * q) * HH + (hc) * 64 + h;      \
        xr[it][0] = src[0 * HH]; xr[it][1] = src[1 * HH];                     \
        xr[it][2] = src[2 * HH]; xr[it][3] = src[3 * HH];                     \
    } } while (0)

#define STS_X(bsel) do {                                                      \
    float* xt_ = &S[XT_OFF + (bsel) * 4352];                                  \
    _Pragma("unroll")                                                         \
    for (int it = 0; it < 8; ++it) {                                          \
        int q = wq + 4 * (it & 3);                                            \
        int h = hlane + 32 * (it >> 2);                                       \
        *(float4*)&xt_[h * 68 + 4 * q] =                                      \
            make_float4(xr[it][0], xr[it][1], xr[it][2], xr[it][3]);          \
    } } while (0)

#define CPA_W2(hc, bsel) do {                                                 \
    uint32_t dst_ = sbase + (uint32_t)(W2_OFF + (bsel) * 4096) * 4u;          \
    const float* src_ = g_W2 + (hc) * 4096;                                   \
    _Pragma("unroll")                                                         \
    for (int i = 0; i < 8; ++i) {                                             \
        int g = tid + 128 * i;                                                \
        cpa16(dst_ + (uint32_t)g * 16u, src_ + g * 4);                        \
    } } while (0)

    // ---------------- prologue ----------------
    CPA_W2(0, 0);
    {   // prefetch char chunks 0+1 (2560 floats, contiguous; u<32 < UU)
        uint32_t dst = sbase + (uint32_t)CH_OFF * 4u;
#pragma unroll
        for (int i = 0; i < 5; ++i) {
            int g = tid + 128 * i;
            cpa16(dst + (uint32_t)g * 16u, cb + g * 4);
        }
    }
    CPA_COMMIT();
    LDG_X(0); STS_X(0);
    LDG_X(1);
    CPA_WAIT0();
    __syncthreads();

    // ---------------- GEMM1 pipeline ----------------
#pragma unroll 1
    for (int hc = 0; hc < 8; ++hc) {
        const int bsel = hc & 1;
        if (hc + 1 < 8) { CPA_W2(hc + 1, bsel ^ 1); CPA_COMMIT(); STS_X(bsel ^ 1); }
        if (hc + 2 < 8) LDG_X(hc + 2);

        const float* xt = &S[XT_OFF + bsel * 4352];
        const float* w2 = &S[W2_OFF + bsel * 4096];
#pragma unroll 16
        for (int h = 0; h < 64; ++h) {
            F4U2 x;  x.f4  = *(const float4*)&xt[h * 68 + tg * 4];
            F4U2 wa; wa.f4 = *(const float4*)&w2[h * 64 + pg * 8];
            F4U2 wb; wb.f4 = *(const float4*)&w2[h * 64 + pg * 8 + 4];
            FMA2(acc[0][0], x.u2[0], wa.u2[0]);
            FMA2(acc[0][1], x.u2[0], wa.u2[1]);
            FMA2(acc[0][2], x.u2[0], wb.u2[0]);
            FMA2(acc[0][3], x.u2[0], wb.u2[1]);
            FMA2(acc[1][0], x.u2[1], wa.u2[0]);
            FMA2(acc[1][1], x.u2[1], wa.u2[1]);
            FMA2(acc[1][2], x.u2[1], wb.u2[0]);
            FMA2(acc[1][3], x.u2[1], wb.u2[1]);
        }
        if (hc + 1 < 8) CPA_WAIT0();
        __syncthreads();
    }

    // ---------------- epilogue: exp -> sABK ----------------
    float* sabk = &S[ABK_OFF];
#pragma unroll
    for (int j = 0; j < 4; ++j) {
        int p = pg * 4 + j;
        if (p < PP) {
#pragma unroll
            for (int tp = 0; tp < 2; ++tp) {
                U64F2 v; v.u = acc[tp][j];
                int tl = 4 * tg + 2 * tp;
                sabk[tl * 33 + p]       = __expf(v.f2.x + bj[j]);
                sabk[(tl + 1) * 33 + p] = __expf(v.f2.y + bj[j]);
            }
        }
    }
    __syncthreads();

    // ---------------- phi setup + cutoff ----------------
    const int tphi = tid & 63, uh = tid >> 6;
    float ra[10], rbl[10], rk[10];
    float um = 1.f;
#pragma unroll
    for (int m = 0; m < 10; ++m) {
        float av = sabk[tphi * 33 + m];
        float bv = sabk[tphi * 33 + 10 + m];
        float kv = sabk[tphi * 33 + 20 + m];
        ra[m] = av; rk[m] = kv;
        um = fmaxf(um, kv + sqrtf(40.f / bv));
        rbl[m] = -1.4426950408889634f * bv;   // phi term = a * 2^(rbl*d^2)
    }
    if (uh == 0)
        atomicMax(iUblk, (int)fminf(ceilf(um) + 2.f, (float)UU));
    __syncthreads();
    const int Ublk = *iUblk;
    const int nch  = (Ublk + 15) >> 4;

    // ---------------- windowed phi + GEMM2 ----------------
    const int tg2 = tid & 15, ag = tid >> 4;      // 4t x 10a tile
    float accO[4][10];
#pragma unroll
    for (int i = 0; i < 4; ++i)
#pragma unroll
        for (int j = 0; j < 10; ++j) accO[i][j] = 0.f;

#pragma unroll 1
    for (int c = 0; c < nch; ++c) {
        const int kb = c & 1;
        if (c >= 2) {   // rare slow path: stage char chunk c (clamped)
            for (int idx = tid; idx < 1280; idx += 128) {
                int u = idx / 80, a = idx - u * 80;
                int gu = c * 16 + u; if (gu >= UU) gu = UU - 1;
                S[CH_OFF + kb * 1280 + idx] = cb[gu * AA + a];
            }
        }
        float* sphi = &S[PH_OFF + kb * 1088];
#pragma unroll
        for (int r = 0; r < 8; ++r) {
            float uf = (float)(c * 16 + uh * 8 + r);
            float s = 0.f;
#pragma unroll
            for (int m = 0; m < 10; ++m) {
                float d = rk[m] - uf;
                float e; EX2A(e, rbl[m] * d * d);
                s = fmaf(ra[m], e, s);
            }
            sphi[(uh * 8 + r) * 68 + tphi] = s;
        }
        __syncthreads();

        const float* sch = &S[CH_OFF + kb * 1280];
#pragma unroll 4
        for (int u = 0; u < 16; ++u) {
            float4 ph = *(const float4*)&sphi[u * 68 + tg2 * 4];
            const float2* cp2 = (const float2*)&sch[u * 80 + ag * 10];
            float2 c01 = cp2[0], c23 = cp2[1], c45 = cp2[2], c67 = cp2[3], c89 = cp2[4];
            float cc[10] = {c01.x, c01.y, c23.x, c23.y, c45.x,
                            c45.y, c67.x, c67.y, c89.x, c89.y};
#pragma unroll
            for (int j = 0; j < 10; ++j) {
                accO[0][j] = fmaf(ph.x, cc[j], accO[0][j]);
                accO[1][j] = fmaf(ph.y, cc[j], accO[1][j]);
                accO[2][j] = fmaf(ph.z, cc[j], accO[2][j]);
                accO[3][j] = fmaf(ph.w, cc[j], accO[3][j]);
            }
        }
        // no trailing sync: next phi writes the other sPhi buffer; the next
        // iteration's sync orders everything before any buffer reuse.
    }

    // ---------------- store ----------------
#pragma unroll
    for (int i = 0; i < 4; ++i) {
        float* orow = out + (size_t)(row0 + tg2 * 4 + i) * AA + ag * 10;
#pragma unroll
        for (int j2 = 0; j2 < 5; ++j2)
            *(float2*)&orow[j2 * 2] = make_float2(accO[i][2 * j2], accO[i][2 * j2 + 1]);
    }
}

extern "C" void kernel_launch(void* const* d_in, const int* in_sizes, int n_in,
                              void* d_out, int out_size)
{
    const float* lstm = (const float*)d_in[0];  // [16,1024,512]
    const float* chs  = (const float*)d_in[1];  // [16,600,80]
    const float* W    = (const float*)d_in[2];  // [512,30]
    const float* bias = (const float*)d_in[3];  // [30]
    float* out = (float*)d_out;                 // [16,1024,80]
    (void)in_sizes; (void)n_in; (void)out_size;

    cudaFuncSetAttribute(fused, cudaFuncAttributeMaxDynamicSharedMemorySize, SMEM_BYTES);
    k0_dupW<<<128, 256>>>(W);
    fused<<<256, 128, SMEM_BYTES>>>(lstm, chs, bias, out);
}